// round 8
// baseline (speedup 1.0000x reference)
#include <cuda_runtime.h>
#include <cuda_fp16.h>
#include <cstdint>

#define BB   4
#define TT   8
#define NN   4096
#define CIN  64
#define C0V  64
#define C1V  128
#define MM   1024
#define KK   32

__device__ int   g_aidx[BB*TT*MM];
__device__ int   g_ball[BB*TT*3*MM*KK];
__device__ float g_xf[(size_t)BB*TT*NN*C0V];

__device__ __forceinline__ float sq3(float dx, float dy, float dz) {
    return __fadd_rn(__fadd_rn(__fmul_rn(dx,dx), __fmul_rn(dy,dy)), __fmul_rn(dz,dz));
}
__device__ __forceinline__ uint32_t packh2(float a, float b) {
    __half2 h = __floats2half2_rn(a, b);
    return *reinterpret_cast<uint32_t*>(&h);
}
__device__ __forceinline__ void mma_f16(float c[4], const uint32_t a[4], const uint32_t b[2]) {
    asm volatile(
        "mma.sync.aligned.m16n8k16.row.col.f32.f16.f16.f32 "
        "{%0,%1,%2,%3}, {%4,%5,%6,%7}, {%8,%9}, {%0,%1,%2,%3};"
        : "+f"(c[0]), "+f"(c[1]), "+f"(c[2]), "+f"(c[3])
        : "r"(a[0]), "r"(a[1]), "r"(a[2]), "r"(a[3]), "r"(b[0]), "r"(b[1]));
}

// ---------------- Kernel A: Xf = relu(Wf . features) -------------------------------
__global__ __launch_bounds__(256) void xf_kernel(const float* __restrict__ feat,
                                                 const float* __restrict__ Wf) {
    int bt = blockIdx.x;
    int p0 = blockIdx.y * 64;
    __shared__ float sWfT[CIN*C0V];
    __shared__ float sF[CIN*64];
    int tid = threadIdx.x;
    for (int e = tid; e < CIN*C0V; e += 256) {
        int o = e / CIN, c = e % CIN;
        sWfT[c*C0V + o] = Wf[e];
    }
    const float* fb = feat + (size_t)bt*CIN*NN + p0;
    for (int e = tid; e < CIN*64; e += 256) {
        int c = e >> 6, p = e & 63;
        sF[e] = fb[(size_t)c*NN + p];
    }
    __syncthreads();
    float* xb = g_xf + ((size_t)bt*NN + p0)*C0V;
    #pragma unroll 4
    for (int r = 0; r < 16; r++) {
        int e = r*256 + tid;
        int p = e >> 6, o = e & 63;
        float s = 0.f;
        #pragma unroll
        for (int c = 0; c < CIN; c++)
            s = fmaf(sWfT[c*C0V + o], sF[c*64 + p], s);
        xb[(size_t)p*C0V + o] = fmaxf(s, 0.f);
    }
}

// ---------------- Kernel B: FPS (512 thr x 8 pts, packed 64-bit argmax keys) -------
__global__ __launch_bounds__(512) void fps_kernel(const float* __restrict__ xyzs) {
    __shared__ unsigned long long sKey[2][16];
    int bt  = blockIdx.x;
    int tid = threadIdx.x;
    const float* xb = xyzs + (size_t)bt*NN*3;

    float px[8], py[8], pz[8], pd[8];
    #pragma unroll
    for (int j = 0; j < 8; j++) {
        int p = tid + j*512;
        px[j] = xb[p*3+0]; py[j] = xb[p*3+1]; pz[j] = xb[p*3+2];
        pd[j] = 1e10f;
    }
    int* aout = g_aidx + bt*MM;
    if (tid == 0) aout[0] = 0;
    float lx = xb[0], ly = xb[1], lz = xb[2];
    int lane = tid & 31, wid = tid >> 5;

    for (int it = 1; it < MM; it++) {
        unsigned long long key = 0;
        #pragma unroll
        for (int j = 0; j < 8; j++) {
            pd[j] = fminf(pd[j], sq3(px[j]-lx, py[j]-ly, pz[j]-lz));
            unsigned long long k =
                ((unsigned long long)__float_as_uint(pd[j]) << 32) | (uint32_t)~(uint32_t)(tid + j*512);
            if (k > key) key = k;
        }
        #pragma unroll
        for (int o = 16; o > 0; o >>= 1) {
            unsigned long long ok = __shfl_xor_sync(0xffffffffu, key, o);
            if (ok > key) key = ok;
        }
        if (lane == 0) sKey[it & 1][wid] = key;
        __syncthreads();
        unsigned long long bk = sKey[it & 1][lane & 15];
        #pragma unroll
        for (int o = 8; o > 0; o >>= 1) {
            unsigned long long ok = __shfl_xor_sync(0xffffffffu, bk, o);
            if (ok > bk) bk = ok;
        }
        int ix = (int)~(uint32_t)bk;
        if (tid == 0) aout[it] = ix;
        lx = xb[ix*3+0]; ly = xb[ix*3+1]; lz = xb[ix*3+2];
    }
}

// ---------------- Kernel E: new_xyzs ----------------------------------------------
__global__ __launch_bounds__(256) void anchor_kernel(const float* __restrict__ xyzs,
                                                     float* __restrict__ outxyz) {
    int idx = blockIdx.x*256 + threadIdx.x;
    if (idx >= BB*TT*MM) return;
    int bt = idx / MM;
    int a  = g_aidx[idx];
    const float* s = xyzs + ((size_t)bt*NN + a)*3;
    float* d = outxyz + (size_t)idx*3;
    d[0] = s[0]; d[1] = s[1]; d[2] = s[2];
}

// ---------------- Kernel C: ball query, 4 points/lane/iteration --------------------
__global__ __launch_bounds__(256) void ball_kernel(const float* __restrict__ xyzs) {
    extern __shared__ float sm[];
    float* px = sm; float* py = sm + NN; float* pz = sm + 2*NN;
    int g  = blockIdx.x;
    int b  = g / (TT*3);
    int r  = g % (TT*3);
    int to = r / 3, i = r % 3;
    int ti = min(max(to + i - 1, 0), TT-1);
    int tid = threadIdx.x;
    const float* fb = xyzs + ((size_t)(b*TT+ti))*NN*3;
    for (int p = tid; p < NN; p += 256) {
        px[p] = fb[p*3+0]; py[p] = fb[p*3+1]; pz[p] = fb[p*3+2];
    }
    __syncthreads();
    const float RR = (float)(0.2*0.2);
    int warp = tid >> 5, lane = tid & 31;
    unsigned lmask = (1u << lane) - 1u;
    for (int mi = 0; mi < 16; mi++) {
        int m = (blockIdx.y*8 + warp)*16 + mi;
        int aidx = g_aidx[(b*TT+to)*MM + m];
        const float* ap = xyzs + ((size_t)(b*TT+to)*NN + aidx)*3;
        float ax = ap[0], ay = ap[1], az = ap[2];
        int* dst = g_ball + ((((size_t)(b*TT+to))*3 + i)*MM + m)*KK;
        int cnt = 0, first = 0; bool none = true;
        for (int base = 0; base < NN && cnt < KK; base += 128) {
            bool in[4];
            #pragma unroll
            for (int j = 0; j < 4; j++) {
                int p = base + 32*j + lane;
                in[j] = sq3(px[p]-ax, py[p]-ay, pz[p]-az) < RR;
            }
            #pragma unroll
            for (int j = 0; j < 4; j++) {
                unsigned mask = __ballot_sync(0xffffffffu, in[j]);
                if (mask) {
                    if (none) { first = base + 32*j + __ffs(mask) - 1; none = false; }
                    int off = cnt + __popc(mask & lmask);
                    if (in[j] && off < KK) dst[off] = base + 32*j + lane;
                    cnt = min(KK, cnt + __popc(mask));
                }
            }
        }
        int pad = none ? 0 : first;
        if (lane >= cnt) dst[lane] = pad;
    }
}

// ---------------- Kernel D: pipelined fused conv (fp16 MMA) ------------------------
// 3-stage pipeline per anchor ml:
//   S1(ml+2): ball idx + neighbor xyz  -> regs (pre-MMA) -> sIdx/sD4[(ml+2)&1] (post-MMA)
//   S2(ml+1): xf gather -> regs (pre-MMA) -> dfeat+pack -> sFeat[(ml+1)&1] (post-MMA)
//   MMA(ml):  on sFeat[ml&1]; pool -> sPool; 2 syncs/anchor.
__global__ __launch_bounds__(256) void conv_kernel(const float* __restrict__ xyzs,
                                                   const float* __restrict__ Wd,
                                                   const float* __restrict__ W1,
                                                   float* __restrict__ outf) {
    __shared__ uint32_t sFeat[2][96*36];            // 27.6 KB
    __shared__ float4   sWd4[C0V];                  // 1 KB
    __shared__ float4   sD4[2][96];                 // 3 KB
    __shared__ int      sIdx[2][96];
    __shared__ float4   sAnch[32];
    __shared__ float    sPool[4][C1V];              // 2 KB
    __shared__ float    sAcc[C1V*17];               // 8.7 KB (16-anchor chunks)

    int blk = blockIdx.x;
    int bt  = blk >> 5;
    int m0  = (blk & 31) * 32;
    int b   = bt / TT, to = bt % TT;
    int tid = threadIdx.x;
    int lane = tid & 31;
    int l4  = lane >> 2, lr = lane & 3;
    int wd8 = tid >> 5;
    int mi  = wd8 >> 2, nq = wd8 & 3;
    int warpN = nq * 32;

    // W1^T fp16 fragments (32 regs)
    uint32_t bf[4][4][2];
    #pragma unroll
    for (int kt = 0; kt < 4; kt++)
        #pragma unroll
        for (int nt = 0; nt < 4; nt++) {
            int n  = warpN + nt*8 + l4;
            int k0 = kt*16 + lr*2;
            bf[kt][nt][0] = packh2(W1[n*C0V + k0],     W1[n*C0V + k0 + 1]);
            bf[kt][nt][1] = packh2(W1[n*C0V + k0 + 8], W1[n*C0V + k0 + 9]);
        }
    if (tid < C0V) sWd4[tid] = ((const float4*)Wd)[tid];
    if (tid < 32) {
        int aidx = g_aidx[bt*MM + m0 + tid];
        const float* ap = xyzs + ((size_t)bt*NN + aidx)*3;
        sAnch[tid] = make_float4(ap[0], ap[1], ap[2], 0.f);
    }
    __syncthreads();

    int s_i  = tid >> 5;                 // frame for S1 role (tid<96)
    int s_ti = min(max(to + s_i - 1, 0), TT-1);

    // prologue: S1(0), S1(1)
    #pragma unroll
    for (int pm = 0; pm < 2; pm++) {
        if (tid < 96) {
            int k = tid & 31;
            int p = g_ball[(((size_t)bt*3 + s_i)*MM + m0 + pm)*KK + k];
            const float* pp = xyzs + ((size_t)(b*TT+s_ti)*NN + p)*3;
            float4 A = sAnch[pm];
            sIdx[pm][tid] = p;
            sD4[pm][tid] = make_float4(pp[0]-A.x, pp[1]-A.y, pp[2]-A.z, (float)(s_i-1));
        }
    }
    __syncthreads();
    // prologue: S2(0) build sFeat[0]
    {
        int cp = tid & 31, r0 = tid >> 5;
        #pragma unroll
        for (int r = 0; r < 12; r++) {
            int row = r0 + 8*r;
            int i = row >> 5;
            int ti = min(max(to + i - 1, 0), TT-1);
            int idx = sIdx[0][row];
            float2 ff = *(const float2*)(g_xf + ((size_t)(b*TT+ti)*NN + idx)*C0V + 2*cp);
            float4 wd0 = sWd4[2*cp], wd1 = sWd4[2*cp+1];
            float4 d4 = sD4[0][row];
            float df0 = wd0.x*d4.x + wd0.y*d4.y + wd0.z*d4.z + wd0.w*d4.w;
            float df1 = wd1.x*d4.x + wd1.y*d4.y + wd1.z*d4.z + wd1.w*d4.w;
            sFeat[0][row*36 + cp] = packh2(ff.x + fmaxf(df0, 0.f), ff.y + fmaxf(df1, 0.f));
        }
    }
    __syncthreads();

    for (int ml = 0; ml < 32; ml++) {
        int cur = ml & 1;
        // ---- S1(ml+2) load phase ----
        int  s1ml = ml + 2;
        bool act1 = (s1ml < 32) && (tid < 96);
        int   p1 = 0; float p1x=0, p1y=0, p1z=0; float4 A1 = {};
        if (act1) {
            int k = tid & 31;
            p1 = g_ball[(((size_t)bt*3 + s_i)*MM + m0 + s1ml)*KK + k];
            const float* pp = xyzs + ((size_t)(b*TT+s_ti)*NN + p1)*3;
            p1x = pp[0]; p1y = pp[1]; p1z = pp[2];
            A1 = sAnch[s1ml];
        }
        // ---- S2(ml+1) load phase ----
        int  s2ml = ml + 1;
        bool act2 = (s2ml < 32);
        int  cp = tid & 31, r0 = tid >> 5;
        float2 xf2[12];
        if (act2) {
            int nb = s2ml & 1;
            #pragma unroll
            for (int r = 0; r < 12; r++) {
                int row = r0 + 8*r;
                int i = row >> 5;
                int ti = min(max(to + i - 1, 0), TT-1);
                int idx = sIdx[nb][row];
                xf2[r] = *(const float2*)(g_xf + ((size_t)(b*TT+ti)*NN + idx)*C0V + 2*cp);
            }
        }

        // ---- MMA(ml) on sFeat[cur] ----
        float c[3][4][4] = {};
        #pragma unroll
        for (int kt = 0; kt < 4; kt++) {
            uint32_t a[3][4];
            #pragma unroll
            for (int mt = 0; mt < 3; mt++) {
                int row = (mi*3 + mt)*16 + l4;
                int col = kt*8 + lr;
                a[mt][0] = sFeat[cur][row*36 + col];
                a[mt][1] = sFeat[cur][(row+8)*36 + col];
                a[mt][2] = sFeat[cur][row*36 + col + 4];
                a[mt][3] = sFeat[cur][(row+8)*36 + col + 4];
            }
            #pragma unroll
            for (int mt = 0; mt < 3; mt++)
                #pragma unroll
                for (int nt = 0; nt < 4; nt++)
                    mma_f16(c[mt][nt], a[mt], bf[kt][nt]);
        }
        // pool -> sPool
        #pragma unroll
        for (int nt = 0; nt < 4; nt++) {
            float t0v0 = fmaxf(c[0][nt][0], c[0][nt][2]);
            float t0v1 = fmaxf(c[0][nt][1], c[0][nt][3]);
            float t1v0 = fmaxf(c[1][nt][0], c[1][nt][2]);
            float t1v1 = fmaxf(c[1][nt][1], c[1][nt][3]);
            float t2v0 = fmaxf(c[2][nt][0], c[2][nt][2]);
            float t2v1 = fmaxf(c[2][nt][1], c[2][nt][3]);
            float pA0 = (mi == 0) ? fmaxf(t0v0, t1v0) : t0v0;
            float pA1 = (mi == 0) ? fmaxf(t0v1, t1v1) : t0v1;
            float pB0 = (mi == 0) ? t2v0 : fmaxf(t1v0, t2v0);
            float pB1 = (mi == 0) ? t2v1 : fmaxf(t1v1, t2v1);
            #pragma unroll
            for (int o = 4; o <= 16; o <<= 1) {
                pA0 = fmaxf(pA0, __shfl_xor_sync(0xffffffffu, pA0, o));
                pA1 = fmaxf(pA1, __shfl_xor_sync(0xffffffffu, pA1, o));
                pB0 = fmaxf(pB0, __shfl_xor_sync(0xffffffffu, pB0, o));
                pB1 = fmaxf(pB1, __shfl_xor_sync(0xffffffffu, pB1, o));
            }
            if (l4 == 0) {
                int n = warpN + nt*8 + 2*lr;
                if (mi == 0) {
                    sPool[0][n]   = fmaxf(pA0, 0.f);
                    sPool[0][n+1] = fmaxf(pA1, 0.f);
                    sPool[1][n]   = pB0;
                    sPool[1][n+1] = pB1;
                } else {
                    sPool[2][n]   = pA0;
                    sPool[2][n+1] = pA1;
                    sPool[3][n]   = fmaxf(pB0, 0.f);
                    sPool[3][n+1] = fmaxf(pB1, 0.f);
                }
            }
        }

        // ---- S2(ml+1) store phase (gather latency was hidden under MMA) ----
        if (act2) {
            int nb = s2ml & 1;
            #pragma unroll
            for (int r = 0; r < 12; r++) {
                int row = r0 + 8*r;
                float4 wd0 = sWd4[2*cp], wd1 = sWd4[2*cp+1];
                float4 d4 = sD4[nb][row];
                float df0 = wd0.x*d4.x + wd0.y*d4.y + wd0.z*d4.z + wd0.w*d4.w;
                float df1 = wd1.x*d4.x + wd1.y*d4.y + wd1.z*d4.z + wd1.w*d4.w;
                sFeat[nb][row*36 + cp] = packh2(xf2[r].x + fmaxf(df0, 0.f),
                                                xf2[r].y + fmaxf(df1, 0.f));
            }
        }
        // ---- S1(ml+2) store phase ----
        if (act1) {
            int nb = s1ml & 1;
            sIdx[nb][tid] = p1;
            sD4[nb][tid] = make_float4(p1x-A1.x, p1y-A1.y, p1z-A1.z, (float)(s_i-1));
        }
        __syncthreads();

        // combine -> sAcc
        if (tid < C1V) {
            float f1 = fmaxf(sPool[1][tid], sPool[2][tid]);
            sAcc[tid*17 + (ml & 15)] = (sPool[0][tid] + fmaxf(f1, 0.f)) + sPool[3][tid];
        }
        if ((ml & 15) == 15) {
            __syncthreads();
            int mbase = m0 + (ml - 15);
            float* ob = outf + ((size_t)bt*C1V)*MM + mbase;
            #pragma unroll
            for (int j = 0; j < 8; j++) {
                int e = j*256 + tid;
                int row = e >> 4, col = e & 15;
                ob[(size_t)row*MM + col] = sAcc[row*17 + col];
            }
        }
        __syncthreads();
    }
}

// ---------------- launch -----------------------------------------------------------
extern "C" void kernel_launch(void* const* d_in, const int* in_sizes, int n_in,
                              void* d_out, int out_size) {
    const float* xyzs = (const float*)d_in[0];
    const float* feat = (const float*)d_in[1];
    const float* Wd   = (const float*)d_in[2];
    const float* Wf   = (const float*)d_in[3];
    const float* W1   = (const float*)d_in[4];
    float* out_xyz = (float*)d_out;
    float* out_f   = (float*)d_out + (size_t)BB*TT*MM*3;

    xf_kernel<<<dim3(BB*TT, NN/64), 256>>>(feat, Wf);
    fps_kernel<<<BB*TT, 512>>>(xyzs);
    anchor_kernel<<<(BB*TT*MM + 255)/256, 256>>>(xyzs, out_xyz);
    ball_kernel<<<dim3(BB*TT*3, 8), 256, 3*NN*sizeof(float)>>>(xyzs);
    conv_kernel<<<BB*TT*32, 256>>>(xyzs, Wd, W1, out_f);
}

// round 9
// speedup vs baseline: 1.1098x; 1.1098x over previous
#include <cuda_runtime.h>
#include <cuda_fp16.h>
#include <cstdint>

#define BB   4
#define TT   8
#define NN   4096
#define CIN  64
#define C0V  64
#define C1V  128
#define MM   1024
#define KK   32

__device__ int   g_aidx[BB*TT*MM];
__device__ int   g_ball[BB*TT*3*MM*KK];
__device__ float g_xf[(size_t)BB*TT*NN*C0V];

__device__ __forceinline__ float sq3(float dx, float dy, float dz) {
    return __fadd_rn(__fadd_rn(__fmul_rn(dx,dx), __fmul_rn(dy,dy)), __fmul_rn(dz,dz));
}
__device__ __forceinline__ uint32_t packh2(float a, float b) {
    __half2 h = __floats2half2_rn(a, b);
    return *reinterpret_cast<uint32_t*>(&h);
}
__device__ __forceinline__ void mma_f16(float c[4], const uint32_t a[4], const uint32_t b[2]) {
    asm volatile(
        "mma.sync.aligned.m16n8k16.row.col.f32.f16.f16.f32 "
        "{%0,%1,%2,%3}, {%4,%5,%6,%7}, {%8,%9}, {%0,%1,%2,%3};"
        : "+f"(c[0]), "+f"(c[1]), "+f"(c[2]), "+f"(c[3])
        : "r"(a[0]), "r"(a[1]), "r"(a[2]), "r"(a[3]), "r"(b[0]), "r"(b[1]));
}

// ---- packed f32x2 helpers (per-lane .rn => bit-exact vs scalar __fadd_rn/__fmul_rn)
__device__ __forceinline__ unsigned long long pk2(float a, float b) {
    unsigned long long r;
    asm("mov.b64 %0, {%1, %2};" : "=l"(r) : "f"(a), "f"(b));
    return r;
}
__device__ __forceinline__ void upk2(float& a, float& b, unsigned long long v) {
    asm("mov.b64 {%0, %1}, %2;" : "=f"(a), "=f"(b) : "l"(v));
}
__device__ __forceinline__ unsigned long long add2(unsigned long long a, unsigned long long b) {
    unsigned long long r;
    asm("add.rn.f32x2 %0, %1, %2;" : "=l"(r) : "l"(a), "l"(b));
    return r;
}
__device__ __forceinline__ unsigned long long mul2(unsigned long long a, unsigned long long b) {
    unsigned long long r;
    asm("mul.rn.f32x2 %0, %1, %2;" : "=l"(r) : "l"(a), "l"(b));
    return r;
}
// packed squared distance of 2 points vs (negated) anchor; exact per lane
__device__ __forceinline__ unsigned long long sq3_2(unsigned long long x2, unsigned long long y2,
                                                    unsigned long long z2, unsigned long long nax2,
                                                    unsigned long long nay2, unsigned long long naz2) {
    unsigned long long dx = add2(x2, nax2);
    unsigned long long dy = add2(y2, nay2);
    unsigned long long dz = add2(z2, naz2);
    return add2(add2(mul2(dx,dx), mul2(dy,dy)), mul2(dz,dz));
}

// ---------------- Kernel A: Xf = relu(Wf . features) -------------------------------
__global__ __launch_bounds__(256) void xf_kernel(const float* __restrict__ feat,
                                                 const float* __restrict__ Wf) {
    int bt = blockIdx.x;
    int p0 = blockIdx.y * 64;
    __shared__ float sWfT[CIN*C0V];
    __shared__ float sF[CIN*64];
    int tid = threadIdx.x;
    for (int e = tid; e < CIN*C0V; e += 256) {
        int o = e / CIN, c = e % CIN;
        sWfT[c*C0V + o] = Wf[e];
    }
    const float* fb = feat + (size_t)bt*CIN*NN + p0;
    for (int e = tid; e < CIN*64; e += 256) {
        int c = e >> 6, p = e & 63;
        sF[e] = fb[(size_t)c*NN + p];
    }
    __syncthreads();
    float* xb = g_xf + ((size_t)bt*NN + p0)*C0V;
    #pragma unroll 4
    for (int r = 0; r < 16; r++) {
        int e = r*256 + tid;
        int p = e >> 6, o = e & 63;
        float s = 0.f;
        #pragma unroll
        for (int c = 0; c < CIN; c++)
            s = fmaf(sWfT[c*C0V + o], sF[c*64 + p], s);
        xb[(size_t)p*C0V + o] = fmaxf(s, 0.f);
    }
}

// ---------------- Kernel B: FPS, 256 threads x 16 pts (8 packed pairs) -------------
// Pair j: points (tid + 256j, tid + 256j + 2048). Packed f32x2 distance math,
// redux.sync warp argmax, 8-winner serial fold (all threads redundantly).
__global__ __launch_bounds__(256) void fps_kernel(const float* __restrict__ xyzs) {
    __shared__ unsigned long long sW[2][8];
    int bt  = blockIdx.x;
    int tid = threadIdx.x;
    const float* xb = xyzs + (size_t)bt*NN*3;

    unsigned long long px2[8], py2[8], pz2[8];
    float pdl[8], pdh[8];
    #pragma unroll
    for (int j = 0; j < 8; j++) {
        int lo = tid + 256*j, hi = lo + 2048;
        px2[j] = pk2(xb[lo*3+0], xb[hi*3+0]);
        py2[j] = pk2(xb[lo*3+1], xb[hi*3+1]);
        pz2[j] = pk2(xb[lo*3+2], xb[hi*3+2]);
        pdl[j] = 1e10f; pdh[j] = 1e10f;
    }
    int* aout = g_aidx + bt*MM;
    if (tid == 0) aout[0] = 0;
    float lx = xb[0], ly = xb[1], lz = xb[2];
    int lane = tid & 31, wid = tid >> 5;

    for (int it = 1; it < MM; it++) {
        unsigned long long nax2 = pk2(-lx, -lx);
        unsigned long long nay2 = pk2(-ly, -ly);
        unsigned long long naz2 = pk2(-lz, -lz);
        uint32_t bv = 0; uint32_t bi = 0;
        #pragma unroll
        for (int j = 0; j < 8; j++) {
            unsigned long long s2 = sq3_2(px2[j], py2[j], pz2[j], nax2, nay2, naz2);
            float s0, s1; upk2(s0, s1, s2);
            pdl[j] = fminf(pdl[j], s0);
            pdh[j] = fminf(pdh[j], s1);
            uint32_t b0 = __float_as_uint(pdl[j]);         // >=0 floats: bits monotonic
            uint32_t b1 = __float_as_uint(pdh[j]);
            uint32_t i0 = (uint32_t)(tid + 256*j);
            uint32_t i1 = i0 + 2048u;
            if (b0 > bv || (b0 == bv && i0 < bi)) { bv = b0; bi = i0; }
            if (b1 > bv || (b1 == bv && i1 < bi)) { bv = b1; bi = i1; }
        }
        uint32_t wmax = __reduce_max_sync(0xffffffffu, bv);
        uint32_t cand = (bv == wmax) ? bi : 0xffffffffu;
        uint32_t widx = __reduce_min_sync(0xffffffffu, cand);
        if (lane == 0)
            sW[it & 1][wid] = ((unsigned long long)wmax << 32) | (uint32_t)~widx;
        __syncthreads();
        unsigned long long best = sW[it & 1][0];
        #pragma unroll
        for (int w = 1; w < 8; w++) {
            unsigned long long k = sW[it & 1][w];
            if (k > best) best = k;
        }
        int ix = (int)~(uint32_t)best;
        if (tid == 0) aout[it] = ix;
        lx = xb[ix*3+0]; ly = xb[ix*3+1]; lz = xb[ix*3+2];   // broadcast L1 hit
    }
}

// ---------------- Kernel E: new_xyzs ----------------------------------------------
__global__ __launch_bounds__(256) void anchor_kernel(const float* __restrict__ xyzs,
                                                     float* __restrict__ outxyz) {
    int idx = blockIdx.x*256 + threadIdx.x;
    if (idx >= BB*TT*MM) return;
    int bt = idx / MM;
    int a  = g_aidx[idx];
    const float* s = xyzs + ((size_t)bt*NN + a)*3;
    float* d = outxyz + (size_t)idx*3;
    d[0] = s[0]; d[1] = s[1]; d[2] = s[2];
}

// ---------------- Kernel C: ball query, packed pairs -------------------------------
// smem holds u64 slots: slot g*32+j = (x[g*64+j], x[g*64+j+32]) so one LDS.64 feeds
// a packed distance for two points whose ballots stay in ascending index order.
__global__ __launch_bounds__(256) void ball_kernel(const float* __restrict__ xyzs) {
    extern __shared__ unsigned long long sm64[];   // 3 * 2048 u64 = 48 KB
    unsigned long long* px = sm64;
    unsigned long long* py = sm64 + NN/2;
    unsigned long long* pz = sm64 + NN;
    int g  = blockIdx.x;
    int b  = g / (TT*3);
    int r  = g % (TT*3);
    int to = r / 3, i = r % 3;
    int ti = min(max(to + i - 1, 0), TT-1);
    int tid = threadIdx.x;
    const float* fb = xyzs + ((size_t)(b*TT+ti))*NN*3;
    for (int s = tid; s < NN/2; s += 256) {
        int grp = s >> 5, j = s & 31;
        int p0 = grp*64 + j, p1 = p0 + 32;
        px[s] = pk2(fb[p0*3+0], fb[p1*3+0]);
        py[s] = pk2(fb[p0*3+1], fb[p1*3+1]);
        pz[s] = pk2(fb[p0*3+2], fb[p1*3+2]);
    }
    __syncthreads();
    const float RR = (float)(0.2*0.2);
    int warp = tid >> 5, lane = tid & 31;
    unsigned lmask = (1u << lane) - 1u;
    for (int mi = 0; mi < 16; mi++) {
        int m = (blockIdx.y*8 + warp)*16 + mi;
        int aidx = g_aidx[(b*TT+to)*MM + m];
        const float* ap = xyzs + ((size_t)(b*TT+to)*NN + aidx)*3;
        unsigned long long nax2 = pk2(-ap[0], -ap[0]);
        unsigned long long nay2 = pk2(-ap[1], -ap[1]);
        unsigned long long naz2 = pk2(-ap[2], -ap[2]);
        int* dst = g_ball + ((((size_t)(b*TT+to))*3 + i)*MM + m)*KK;
        int cnt = 0, first = 0; bool none = true;
        for (int base = 0; base < NN && cnt < KK; base += 64) {
            int s = (base >> 1) + lane;
            unsigned long long d2 = sq3_2(px[s], py[s], pz[s], nax2, nay2, naz2);
            float d0, d1; upk2(d0, d1, d2);
            bool in0 = d0 < RR, in1 = d1 < RR;
            unsigned m0 = __ballot_sync(0xffffffffu, in0);
            if (m0) {
                if (none) { first = base + __ffs(m0) - 1; none = false; }
                int off = cnt + __popc(m0 & lmask);
                if (in0 && off < KK) dst[off] = base + lane;
                cnt = min(KK, cnt + __popc(m0));
            }
            unsigned m1 = __ballot_sync(0xffffffffu, in1);
            if (m1) {
                if (none) { first = base + 32 + __ffs(m1) - 1; none = false; }
                int off = cnt + __popc(m1 & lmask);
                if (in1 && off < KK) dst[off] = base + 32 + lane;
                cnt = min(KK, cnt + __popc(m1));
            }
        }
        int pad = none ? 0 : first;
        if (lane >= cnt) dst[lane] = pad;
    }
}

// ---------------- Kernel D: pipelined fused conv (fp16 MMA) ------------------------
__global__ __launch_bounds__(256) void conv_kernel(const float* __restrict__ xyzs,
                                                   const float* __restrict__ Wd,
                                                   const float* __restrict__ W1,
                                                   float* __restrict__ outf) {
    __shared__ uint32_t sFeat[2][96*36];
    __shared__ float4   sWd4[C0V];
    __shared__ float4   sD4[2][96];
    __shared__ int      sIdx[2][96];
    __shared__ float4   sAnch[32];
    __shared__ float    sPool[4][C1V];
    __shared__ float    sAcc[C1V*17];

    int blk = blockIdx.x;
    int bt  = blk >> 5;
    int m0  = (blk & 31) * 32;
    int b   = bt / TT, to = bt % TT;
    int tid = threadIdx.x;
    int lane = tid & 31;
    int l4  = lane >> 2, lr = lane & 3;
    int wd8 = tid >> 5;
    int mi  = wd8 >> 2, nq = wd8 & 3;
    int warpN = nq * 32;

    uint32_t bf[4][4][2];
    #pragma unroll
    for (int kt = 0; kt < 4; kt++)
        #pragma unroll
        for (int nt = 0; nt < 4; nt++) {
            int n  = warpN + nt*8 + l4;
            int k0 = kt*16 + lr*2;
            bf[kt][nt][0] = packh2(W1[n*C0V + k0],     W1[n*C0V + k0 + 1]);
            bf[kt][nt][1] = packh2(W1[n*C0V + k0 + 8], W1[n*C0V + k0 + 9]);
        }
    if (tid < C0V) sWd4[tid] = ((const float4*)Wd)[tid];
    if (tid < 32) {
        int aidx = g_aidx[bt*MM + m0 + tid];
        const float* ap = xyzs + ((size_t)bt*NN + aidx)*3;
        sAnch[tid] = make_float4(ap[0], ap[1], ap[2], 0.f);
    }
    __syncthreads();

    int s_i  = tid >> 5;
    int s_ti = min(max(to + s_i - 1, 0), TT-1);

    #pragma unroll
    for (int pm = 0; pm < 2; pm++) {
        if (tid < 96) {
            int k = tid & 31;
            int p = g_ball[(((size_t)bt*3 + s_i)*MM + m0 + pm)*KK + k];
            const float* pp = xyzs + ((size_t)(b*TT+s_ti)*NN + p)*3;
            float4 A = sAnch[pm];
            sIdx[pm][tid] = p;
            sD4[pm][tid] = make_float4(pp[0]-A.x, pp[1]-A.y, pp[2]-A.z, (float)(s_i-1));
        }
    }
    __syncthreads();
    {
        int cp = tid & 31, r0 = tid >> 5;
        #pragma unroll
        for (int r = 0; r < 12; r++) {
            int row = r0 + 8*r;
            int i = row >> 5;
            int ti = min(max(to + i - 1, 0), TT-1);
            int idx = sIdx[0][row];
            float2 ff = *(const float2*)(g_xf + ((size_t)(b*TT+ti)*NN + idx)*C0V + 2*cp);
            float4 wd0 = sWd4[2*cp], wd1 = sWd4[2*cp+1];
            float4 d4 = sD4[0][row];
            float df0 = wd0.x*d4.x + wd0.y*d4.y + wd0.z*d4.z + wd0.w*d4.w;
            float df1 = wd1.x*d4.x + wd1.y*d4.y + wd1.z*d4.z + wd1.w*d4.w;
            sFeat[0][row*36 + cp] = packh2(ff.x + fmaxf(df0, 0.f), ff.y + fmaxf(df1, 0.f));
        }
    }
    __syncthreads();

    for (int ml = 0; ml < 32; ml++) {
        int cur = ml & 1;
        int  s1ml = ml + 2;
        bool act1 = (s1ml < 32) && (tid < 96);
        int   p1 = 0; float p1x=0, p1y=0, p1z=0; float4 A1 = {};
        if (act1) {
            int k = tid & 31;
            p1 = g_ball[(((size_t)bt*3 + s_i)*MM + m0 + s1ml)*KK + k];
            const float* pp = xyzs + ((size_t)(b*TT+s_ti)*NN + p1)*3;
            p1x = pp[0]; p1y = pp[1]; p1z = pp[2];
            A1 = sAnch[s1ml];
        }
        int  s2ml = ml + 1;
        bool act2 = (s2ml < 32);
        int  cp = tid & 31, r0 = tid >> 5;
        float2 xf2[12];
        if (act2) {
            int nb = s2ml & 1;
            #pragma unroll
            for (int r = 0; r < 12; r++) {
                int row = r0 + 8*r;
                int i = row >> 5;
                int ti = min(max(to + i - 1, 0), TT-1);
                int idx = sIdx[nb][row];
                xf2[r] = *(const float2*)(g_xf + ((size_t)(b*TT+ti)*NN + idx)*C0V + 2*cp);
            }
        }

        float c[3][4][4] = {};
        #pragma unroll
        for (int kt = 0; kt < 4; kt++) {
            uint32_t a[3][4];
            #pragma unroll
            for (int mt = 0; mt < 3; mt++) {
                int row = (mi*3 + mt)*16 + l4;
                int col = kt*8 + lr;
                a[mt][0] = sFeat[cur][row*36 + col];
                a[mt][1] = sFeat[cur][(row+8)*36 + col];
                a[mt][2] = sFeat[cur][row*36 + col + 4];
                a[mt][3] = sFeat[cur][(row+8)*36 + col + 4];
            }
            #pragma unroll
            for (int mt = 0; mt < 3; mt++)
                #pragma unroll
                for (int nt = 0; nt < 4; nt++)
                    mma_f16(c[mt][nt], a[mt], bf[kt][nt]);
        }
        #pragma unroll
        for (int nt = 0; nt < 4; nt++) {
            float t0v0 = fmaxf(c[0][nt][0], c[0][nt][2]);
            float t0v1 = fmaxf(c[0][nt][1], c[0][nt][3]);
            float t1v0 = fmaxf(c[1][nt][0], c[1][nt][2]);
            float t1v1 = fmaxf(c[1][nt][1], c[1][nt][3]);
            float t2v0 = fmaxf(c[2][nt][0], c[2][nt][2]);
            float t2v1 = fmaxf(c[2][nt][1], c[2][nt][3]);
            float pA0 = (mi == 0) ? fmaxf(t0v0, t1v0) : t0v0;
            float pA1 = (mi == 0) ? fmaxf(t0v1, t1v1) : t0v1;
            float pB0 = (mi == 0) ? t2v0 : fmaxf(t1v0, t2v0);
            float pB1 = (mi == 0) ? t2v1 : fmaxf(t1v1, t2v1);
            #pragma unroll
            for (int o = 4; o <= 16; o <<= 1) {
                pA0 = fmaxf(pA0, __shfl_xor_sync(0xffffffffu, pA0, o));
                pA1 = fmaxf(pA1, __shfl_xor_sync(0xffffffffu, pA1, o));
                pB0 = fmaxf(pB0, __shfl_xor_sync(0xffffffffu, pB0, o));
                pB1 = fmaxf(pB1, __shfl_xor_sync(0xffffffffu, pB1, o));
            }
            if (l4 == 0) {
                int n = warpN + nt*8 + 2*lr;
                if (mi == 0) {
                    sPool[0][n]   = fmaxf(pA0, 0.f);
                    sPool[0][n+1] = fmaxf(pA1, 0.f);
                    sPool[1][n]   = pB0;
                    sPool[1][n+1] = pB1;
                } else {
                    sPool[2][n]   = pA0;
                    sPool[2][n+1] = pA1;
                    sPool[3][n]   = fmaxf(pB0, 0.f);
                    sPool[3][n+1] = fmaxf(pB1, 0.f);
                }
            }
        }

        if (act2) {
            int nb = s2ml & 1;
            #pragma unroll
            for (int r = 0; r < 12; r++) {
                int row = r0 + 8*r;
                float4 wd0 = sWd4[2*cp], wd1 = sWd4[2*cp+1];
                float4 d4 = sD4[nb][row];
                float df0 = wd0.x*d4.x + wd0.y*d4.y + wd0.z*d4.z + wd0.w*d4.w;
                float df1 = wd1.x*d4.x + wd1.y*d4.y + wd1.z*d4.z + wd1.w*d4.w;
                sFeat[nb][row*36 + cp] = packh2(xf2[r].x + fmaxf(df0, 0.f),
                                                xf2[r].y + fmaxf(df1, 0.f));
            }
        }
        if (act1) {
            int nb = s1ml & 1;
            sIdx[nb][tid] = p1;
            sD4[nb][tid] = make_float4(p1x-A1.x, p1y-A1.y, p1z-A1.z, (float)(s_i-1));
        }
        __syncthreads();

        if (tid < C1V) {
            float f1 = fmaxf(sPool[1][tid], sPool[2][tid]);
            sAcc[tid*17 + (ml & 15)] = (sPool[0][tid] + fmaxf(f1, 0.f)) + sPool[3][tid];
        }
        if ((ml & 15) == 15) {
            __syncthreads();
            int mbase = m0 + (ml - 15);
            float* ob = outf + ((size_t)bt*C1V)*MM + mbase;
            #pragma unroll
            for (int j = 0; j < 8; j++) {
                int e = j*256 + tid;
                int row = e >> 4, col = e & 15;
                ob[(size_t)row*MM + col] = sAcc[row*17 + col];
            }
        }
        __syncthreads();
    }
}

// ---------------- launch -----------------------------------------------------------
extern "C" void kernel_launch(void* const* d_in, const int* in_sizes, int n_in,
                              void* d_out, int out_size) {
    const float* xyzs = (const float*)d_in[0];
    const float* feat = (const float*)d_in[1];
    const float* Wd   = (const float*)d_in[2];
    const float* Wf   = (const float*)d_in[3];
    const float* W1   = (const float*)d_in[4];
    float* out_xyz = (float*)d_out;
    float* out_f   = (float*)d_out + (size_t)BB*TT*MM*3;

    xf_kernel<<<dim3(BB*TT, NN/64), 256>>>(feat, Wf);
    fps_kernel<<<BB*TT, 256>>>(xyzs);
    anchor_kernel<<<(BB*TT*MM + 255)/256, 256>>>(xyzs, out_xyz);
    ball_kernel<<<dim3(BB*TT*3, 8), 256, 3*(NN/2)*sizeof(unsigned long long)>>>(xyzs);
    conv_kernel<<<BB*TT*32, 256>>>(xyzs, Wd, W1, out_f);
}